// round 2
// baseline (speedup 1.0000x reference)
#include <cuda_runtime.h>
#include <math.h>

// Problem constants
#define B_  8
#define T_  4096
#define D_  256           // D_IN == D_OUT == 256
#define M_  (B_ * T_)     // 32768 rows
#define K_  256

// GEMM tiling
#define BM 128
#define BN 128
#define BK 16
#define TM 8
#define TN 8
// 256 threads per block: 16 x 16 thread grid of 8x8 micro-tiles

// Scratch for activations (static device allocation — allowed; no runtime alloc)
__device__ float g_X[(size_t)M_ * D_];   // tanh branch
__device__ float g_F[(size_t)M_ * D_];   // sigmoid branch

// Fused GEMM + activation epilogue.
// Treats the two weight matrices as a concatenated N=512 GEMM:
//   cols [0,256)   -> X = tanh(A @ W_in^T + b_in)
//   cols [256,512) -> F = sigmoid(A @ W_f^T + b_f + mask*10000)
__global__ __launch_bounds__(256, 2)
void gemm_act_kernel(const float* __restrict__ A,      // [M, 256]
                     const float* __restrict__ W_in,   // [256, 256]
                     const float* __restrict__ b_in,   // [256]
                     const float* __restrict__ W_f,    // [256, 256]
                     const float* __restrict__ b_f,    // [256]
                     const float* __restrict__ mask)   // [M] (B*T*1)
{
    __shared__ float As[BK][BM];   // transposed A tile
    __shared__ float Ws[BK][BN];   // transposed W tile

    const int tid = threadIdx.x;
    const int tx  = tid & 15;          // 0..15  -> N direction
    const int ty  = tid >> 4;          // 0..15  -> M direction

    const int m0 = blockIdx.x * BM;
    const int n_base = blockIdx.y * BN;    // 0,128,256,384

    // Whole 128-col block sits entirely inside one weight matrix.
    const bool is_f = (n_base >= D_);
    const float* __restrict__ W = is_f ? (W_f + (size_t)(n_base - D_) * K_)
                                       : (W_in + (size_t)n_base * K_);

    float acc[TM][TN];
#pragma unroll
    for (int i = 0; i < TM; i++)
#pragma unroll
        for (int j = 0; j < TN; j++) acc[i][j] = 0.0f;

    for (int k0 = 0; k0 < K_; k0 += BK) {
        // Load A tile: 128 rows x 16 k  = 512 float4s, 2 per thread
#pragma unroll
        for (int s = 0; s < 2; s++) {
            int li  = tid * 2 + s;
            int row = li >> 2;           // 0..127
            int c   = li & 3;            // 0..3 (float4 within row)
            float4 v = *reinterpret_cast<const float4*>(
                A + (size_t)(m0 + row) * K_ + k0 + c * 4);
            As[c * 4 + 0][row] = v.x;
            As[c * 4 + 1][row] = v.y;
            As[c * 4 + 2][row] = v.z;
            As[c * 4 + 3][row] = v.w;
        }
        // Load W tile: 128 n-rows x 16 k, same pattern
#pragma unroll
        for (int s = 0; s < 2; s++) {
            int li  = tid * 2 + s;
            int row = li >> 2;
            int c   = li & 3;
            float4 v = *reinterpret_cast<const float4*>(
                W + (size_t)row * K_ + k0 + c * 4);
            Ws[c * 4 + 0][row] = v.x;
            Ws[c * 4 + 1][row] = v.y;
            Ws[c * 4 + 2][row] = v.z;
            Ws[c * 4 + 3][row] = v.w;
        }
        __syncthreads();

#pragma unroll
        for (int k = 0; k < BK; k++) {
            float a[TM], b[TN];
#pragma unroll
            for (int i = 0; i < TM; i++) a[i] = As[k][ty * TM + i];
#pragma unroll
            for (int j = 0; j < TN; j++) b[j] = Ws[k][tx * TN + j];
#pragma unroll
            for (int i = 0; i < TM; i++)
#pragma unroll
                for (int j = 0; j < TN; j++)
                    acc[i][j] = fmaf(a[i], b[j], acc[i][j]);
        }
        __syncthreads();
    }

    // Epilogue
    const int mr = m0 + ty * TM;
    const int nc = n_base + tx * TN;

    float bias[TN];
#pragma unroll
    for (int j = 0; j < TN; j++) {
        int n = nc + j;
        bias[j] = is_f ? b_f[n - D_] : b_in[n];
    }

#pragma unroll
    for (int i = 0; i < TM; i++) {
        int m = mr + i;
        float mk = is_f ? mask[m] * 10000.0f : 0.0f;
#pragma unroll
        for (int j = 0; j < TN; j++) {
            int n = nc + j;
            float z = acc[i][j] + bias[j] + mk;
            if (!is_f) {
                g_X[(size_t)m * D_ + n] = tanhf(z);
            } else {
                g_F[(size_t)m * D_ + (n - D_)] = 1.0f / (1.0f + expf(-z));
            }
        }
    }
}

// Sequential forget-mult scan: h_t = f_t*x_t + (1-f_t)*h_{t-1} = h + f*(x-h)
// One thread per (b, d) channel: 2048 threads, 4096 steps each.
// Loads are independent of the h chain -> compiler can prefetch ahead.
__global__ __launch_bounds__(256)
void scan_kernel(float* __restrict__ out)   // [B, T, D]
{
    const int flat = blockIdx.x * blockDim.x + threadIdx.x;  // 0..2047
    if (flat >= B_ * D_) return;
    const int b = flat / D_;
    const int d = flat % D_;

    size_t idx = (size_t)b * T_ * D_ + d;
    float h = 0.0f;

#pragma unroll 4
    for (int t = 0; t < T_; t++) {
        float f = g_F[idx];
        float x = g_X[idx];
        h = fmaf(f, x - h, h);
        out[idx] = h;
        idx += D_;
    }
}

extern "C" void kernel_launch(void* const* d_in, const int* in_sizes, int n_in,
                              void* d_out, int out_size)
{
    const float* inputs = (const float*)d_in[0];   // [B,T,256]
    const float* mask   = (const float*)d_in[1];   // [B,T,1]
    const float* W_in   = (const float*)d_in[2];   // [256,256]
    const float* b_in   = (const float*)d_in[3];   // [256]
    const float* W_f    = (const float*)d_in[4];   // [256,256]
    const float* b_f    = (const float*)d_in[5];   // [256]
    float* out = (float*)d_out;

    dim3 ggrid(M_ / BM, (2 * D_) / BN);   // 256 x 4
    gemm_act_kernel<<<ggrid, 256>>>(inputs, W_in, b_in, W_f, b_f, mask);

    scan_kernel<<<(B_ * D_ + 255) / 256, 256>>>(out);
}

// round 4
// speedup vs baseline: 2.5020x; 2.5020x over previous
#include <cuda_runtime.h>
#include <math.h>

// Problem constants
#define B_  8
#define T_  4096
#define D_  256           // D_IN == D_OUT == 256
#define M_  (B_ * T_)     // 32768 rows
#define K_  256

// GEMM tiling
#define BM 128
#define BN 128
#define BK 16
#define TM 8
#define TN 8

// Scan chunking
#define LCH 32                 // steps per chunk
#define NCH (T_ / LCH)         // 128 chunks per channel
#define NCHAN (B_ * D_)        // 2048 channels

// Scratch (static device allocations — allowed)
__device__ float g_X[(size_t)M_ * D_];          // tanh branch
__device__ float g_F[(size_t)M_ * D_];          // sigmoid branch
__device__ float g_A [NCH * NCHAN];             // chunk decay product,   [c][channel]
__device__ float g_Hl[NCH * NCHAN];             // chunk local final h,   [c][channel]
__device__ float g_H0[NCH * NCHAN];             // chunk entry state,     [c][channel]

// ---------------------------------------------------------------------------
// Fused GEMM + activation epilogue (unchanged from R1: ~64 TF/s fp32, near peak)
// ---------------------------------------------------------------------------
__global__ __launch_bounds__(256, 2)
void gemm_act_kernel(const float* __restrict__ A,      // [M, 256]
                     const float* __restrict__ W_in,   // [256, 256]
                     const float* __restrict__ b_in,   // [256]
                     const float* __restrict__ W_f,    // [256, 256]
                     const float* __restrict__ b_f,    // [256]
                     const float* __restrict__ mask)   // [M]
{
    __shared__ float As[BK][BM];
    __shared__ float Ws[BK][BN];

    const int tid = threadIdx.x;
    const int tx  = tid & 15;
    const int ty  = tid >> 4;

    const int m0 = blockIdx.x * BM;
    const int n_base = blockIdx.y * BN;

    const bool is_f = (n_base >= D_);
    const float* __restrict__ W = is_f ? (W_f + (size_t)(n_base - D_) * K_)
                                       : (W_in + (size_t)n_base * K_);

    float acc[TM][TN];
#pragma unroll
    for (int i = 0; i < TM; i++)
#pragma unroll
        for (int j = 0; j < TN; j++) acc[i][j] = 0.0f;

    for (int k0 = 0; k0 < K_; k0 += BK) {
#pragma unroll
        for (int s = 0; s < 2; s++) {
            int li  = tid * 2 + s;
            int row = li >> 2;
            int c   = li & 3;
            float4 v = *reinterpret_cast<const float4*>(
                A + (size_t)(m0 + row) * K_ + k0 + c * 4);
            As[c * 4 + 0][row] = v.x;
            As[c * 4 + 1][row] = v.y;
            As[c * 4 + 2][row] = v.z;
            As[c * 4 + 3][row] = v.w;
        }
#pragma unroll
        for (int s = 0; s < 2; s++) {
            int li  = tid * 2 + s;
            int row = li >> 2;
            int c   = li & 3;
            float4 v = *reinterpret_cast<const float4*>(
                W + (size_t)row * K_ + k0 + c * 4);
            Ws[c * 4 + 0][row] = v.x;
            Ws[c * 4 + 1][row] = v.y;
            Ws[c * 4 + 2][row] = v.z;
            Ws[c * 4 + 3][row] = v.w;
        }
        __syncthreads();

#pragma unroll
        for (int k = 0; k < BK; k++) {
            float a[TM], b[TN];
#pragma unroll
            for (int i = 0; i < TM; i++) a[i] = As[k][ty * TM + i];
#pragma unroll
            for (int j = 0; j < TN; j++) b[j] = Ws[k][tx * TN + j];
#pragma unroll
            for (int i = 0; i < TM; i++)
#pragma unroll
                for (int j = 0; j < TN; j++)
                    acc[i][j] = fmaf(a[i], b[j], acc[i][j]);
        }
        __syncthreads();
    }

    const int mr = m0 + ty * TM;
    const int nc = n_base + tx * TN;

    float bias[TN];
#pragma unroll
    for (int j = 0; j < TN; j++) {
        int n = nc + j;
        bias[j] = is_f ? b_f[n - D_] : b_in[n];
    }

#pragma unroll
    for (int i = 0; i < TM; i++) {
        int m = mr + i;
        float mk = is_f ? mask[m] * 10000.0f : 0.0f;
#pragma unroll
        for (int j = 0; j < TN; j++) {
            int n = nc + j;
            float z = acc[i][j] + bias[j] + mk;
            if (!is_f) {
                g_X[(size_t)m * D_ + n] = tanhf(z);
            } else {
                g_F[(size_t)m * D_ + (n - D_)] = 1.0f / (1.0f + expf(-z));
            }
        }
    }
}

// ---------------------------------------------------------------------------
// Scan pass 1: per-(channel, chunk) summary.
//   A    = prod over chunk of (1 - f_t)
//   h_loc= chunk-local scan final value with h0 = 0
// block = one (b, chunk): threadIdx.x = d  -> fully coalesced loads.
// ---------------------------------------------------------------------------
__global__ __launch_bounds__(256)
void scan_pass1()
{
    const int b = blockIdx.x / NCH;
    const int c = blockIdx.x % NCH;
    const int d = threadIdx.x;

    size_t idx = ((size_t)(b * T_ + c * LCH)) * D_ + d;
    float h = 0.0f;
    float A = 1.0f;
#pragma unroll
    for (int t = 0; t < LCH; t++) {
        float f = g_F[idx];
        float x = g_X[idx];
        float om = 1.0f - f;
        h = fmaf(f, x, om * h);
        A *= om;
        idx += D_;
    }
    const int ch = b * D_ + d;
    g_A [c * NCHAN + ch] = A;
    g_Hl[c * NCHAN + ch] = h;
}

// ---------------------------------------------------------------------------
// Scan pass 2: per-channel sequential combine over 128 chunk summaries.
// h_entry(c) = h_loc(c-1) + A(c-1) * h_entry(c-1).  [c][channel] layout keeps
// every access coalesced.
// ---------------------------------------------------------------------------
__global__ __launch_bounds__(256)
void scan_pass2()
{
    const int ch = blockIdx.x * blockDim.x + threadIdx.x;  // 0..2047
    float h = 0.0f;
#pragma unroll 8
    for (int c = 0; c < NCH; c++) {
        g_H0[c * NCHAN + ch] = h;
        h = fmaf(g_A[c * NCHAN + ch], h, g_Hl[c * NCHAN + ch]);
    }
}

// ---------------------------------------------------------------------------
// Scan pass 3: re-run each chunk from its correct entry state, write output.
// ---------------------------------------------------------------------------
__global__ __launch_bounds__(256)
void scan_pass3(float* __restrict__ out)
{
    const int b = blockIdx.x / NCH;
    const int c = blockIdx.x % NCH;
    const int d = threadIdx.x;
    const int ch = b * D_ + d;

    float h = g_H0[c * NCHAN + ch];
    size_t idx = ((size_t)(b * T_ + c * LCH)) * D_ + d;
#pragma unroll
    for (int t = 0; t < LCH; t++) {
        float f = g_F[idx];
        float x = g_X[idx];
        h = fmaf(f, x - h, h);
        out[idx] = h;
        idx += D_;
    }
}

extern "C" void kernel_launch(void* const* d_in, const int* in_sizes, int n_in,
                              void* d_out, int out_size)
{
    const float* inputs = (const float*)d_in[0];   // [B,T,256]
    const float* mask   = (const float*)d_in[1];   // [B,T,1]
    const float* W_in   = (const float*)d_in[2];   // [256,256]
    const float* b_in   = (const float*)d_in[3];   // [256]
    const float* W_f    = (const float*)d_in[4];   // [256,256]
    const float* b_f    = (const float*)d_in[5];   // [256]
    float* out = (float*)d_out;

    dim3 ggrid(M_ / BM, (2 * D_) / BN);   // 256 x 4
    gemm_act_kernel<<<ggrid, 256>>>(inputs, W_in, b_in, W_f, b_f, mask);

    scan_pass1<<<B_ * NCH, 256>>>();          // 1024 blocks
    scan_pass2<<<NCHAN / 256, 256>>>();       // 8 blocks
    scan_pass3<<<B_ * NCH, 256>>>(out);       // 1024 blocks
}

// round 6
// speedup vs baseline: 4.6153x; 1.8446x over previous
#include <cuda_runtime.h>
#include <cuda_bf16.h>
#include <math.h>
#include <stdint.h>

// ---------------- problem constants ----------------
#define B_  8
#define T_  4096
#define D_  256
#define M_  (B_ * T_)      // 32768
#define K_  256
#define N_TOT 512

// ---------------- scan chunking ----------------
#define LCH 64
#define NCH (T_ / LCH)     // 64
#define NCHAN (B_ * D_)    // 2048

// ---------------- scratch (static device allocations) ----------------
__device__ __align__(16) float g_X[(size_t)M_ * D_];
__device__ __align__(16) float g_F[(size_t)M_ * D_];
__device__ float g_A [NCH * NCHAN];
__device__ float g_Hl[NCH * NCHAN];
__device__ float g_H0[NCH * NCHAN];
// W split, stored in PERMUTED row order:
//   p = nb*256 + branch*128 + (d&127), where nb = d>>7.
// So block nb reads rows [nb*256, nb*256+256): first 128 = X cols of its d-range,
// next 128 = F cols of the same d-range.
__device__ uint4 g_Whi4[(N_TOT * K_) / 8];
__device__ uint4 g_Wlo4[(N_TOT * K_) / 8];

// ---------------- smem layout (gemm kernel) ----------------
#define SM_AHI   0          // A_hi [64][256] bf16, swizzled, 32KB
#define SM_ALO   32768      // A_lo 32KB
#define SM_W0    65536      // buffer0: WH 32KB + WL 32KB
#define SM_W1    131072     // buffer1
#define SM_WLOFF 32768
#define SM_BIAS  196608     // 256 floats (this block's n_locals)
#define SM_MK    197632     // 64 floats
#define SM_TOTAL 197888
// epilogue staging (reuses A/W space after final sync)
#define SM_XS    0
#define SM_FS    36864
#define STG      136        // row stride in floats

// ---------------- asm helpers (all sm_80-era, no 'a' features) ----------------
__device__ __forceinline__ uint32_t smem_u32(const void* p) {
    uint32_t a;
    asm("{ .reg .u64 t; cvta.to.shared.u64 t, %1; cvt.u32.u64 %0, t; }" : "=r"(a) : "l"(p));
    return a;
}
#define LDSM4(r, addr) asm volatile( \
    "ldmatrix.sync.aligned.m8n8.x4.shared.b16 {%0,%1,%2,%3}, [%4];" \
    : "=r"((r)[0]), "=r"((r)[1]), "=r"((r)[2]), "=r"((r)[3]) : "r"(addr))
#define MMA(d, a, b0v, b1v) asm volatile( \
    "mma.sync.aligned.m16n8k16.row.col.f32.bf16.bf16.f32 " \
    "{%0,%1,%2,%3}, {%4,%5,%6,%7}, {%8,%9}, {%0,%1,%2,%3};" \
    : "+f"((d)[0]), "+f"((d)[1]), "+f"((d)[2]), "+f"((d)[3]) \
    : "r"((a)[0]), "r"((a)[1]), "r"((a)[2]), "r"((a)[3]), "r"(b0v), "r"(b1v))
__device__ __forceinline__ void cp_async16(uint32_t dst, const void* src) {
    asm volatile("cp.async.cg.shared.global [%0], [%1], 16;" :: "r"(dst), "l"(src));
}
#define CP_COMMIT() asm volatile("cp.async.commit_group;" ::: "memory")

// ---------------------------------------------------------------------------
// W precompute: fp32 -> (hi, lo) bf16 split, permuted row order (see above)
// ---------------------------------------------------------------------------
__global__ void wsplit_kernel(const float* __restrict__ W_in, const float* __restrict__ W_f)
{
    int i = blockIdx.x * blockDim.x + threadIdx.x;   // 0 .. 131071
    if (i >= N_TOT * K_) return;
    int p = i >> 8, k = i & 255;
    int nb = p >> 8;
    int rem = p & 255;
    int branch = rem >> 7;
    int d = nb * 128 + (rem & 127);
    float v = branch ? W_f[d * K_ + k] : W_in[d * K_ + k];
    __nv_bfloat16 hi = __float2bfloat16_rn(v);
    ((__nv_bfloat16*)g_Whi4)[i] = hi;
    ((__nv_bfloat16*)g_Wlo4)[i] = __float2bfloat16_rn(v - __bfloat162float(hi));
}

// ---------------------------------------------------------------------------
// Split-bf16 mma.sync GEMM + activations + FUSED chunk-scan summary.
// grid = 1024 blocks (512 m-chunks x 2 n-halves), 512 threads.
// Block (mchunk, nb): rows m0..m0+63 (= one scan chunk of batch b),
//   n_local 0..127 -> X cols d = nb*128+nl ; 128..255 -> F cols same d range.
// ---------------------------------------------------------------------------
__global__ __launch_bounds__(512, 1)
void gemm_mma_kernel(const float* __restrict__ A,
                     const float* __restrict__ b_in,
                     const float* __restrict__ b_f,
                     const float* __restrict__ mask)
{
    extern __shared__ __align__(16) char smem[];
    const uint32_t sb = smem_u32(smem);
    const int tid = threadIdx.x;
    const int w   = tid >> 5, l = tid & 31;
    const int wm  = w >> 3;           // 0..1  (m 32-row half)
    const int wn  = w & 7;            // 0..7  (n 32-col slice)
    const int m0  = (blockIdx.x >> 1) * 64;
    const int nb  = blockIdx.x & 1;

    // bias (permuted to this block's n_local order) + mask*1e4
    for (int i = tid; i < 256; i += 512) {
        int branch = i >> 7;
        int d = nb * 128 + (i & 127);
        *(float*)(smem + SM_BIAS + i * 4) = branch ? b_f[d] : b_in[d];
    }
    if (tid < 64) *(float*)(smem + SM_MK + tid * 4) = mask[m0 + tid] * 10000.0f;

    // A tile [64][256] fp32 -> smem hi/lo bf16 (swizzled, full K)
#pragma unroll
    for (int i = 0; i < 8; i++) {
        int v   = i * 512 + tid;         // float4 id, 4096 total
        int row = v >> 6;
        int col = (v & 63) * 4;
        float4 a = *(const float4*)(A + (size_t)(m0 + row) * K_ + col);
        __nv_bfloat16 h0 = __float2bfloat16_rn(a.x), h1 = __float2bfloat16_rn(a.y),
                      h2 = __float2bfloat16_rn(a.z), h3 = __float2bfloat16_rn(a.w);
        __nv_bfloat162 hp0 = {h0, h1}, hp1 = {h2, h3};
        __nv_bfloat162 lp0 = __floats2bfloat162_rn(a.x - __bfloat162float(h0),
                                                   a.y - __bfloat162float(h1));
        __nv_bfloat162 lp1 = __floats2bfloat162_rn(a.z - __bfloat162float(h2),
                                                   a.w - __bfloat162float(h3));
        uint32_t off = row * 512 + ((((col >> 3) ^ (row & 7))) << 4) + (col & 7) * 2;
        *(uint2*)(smem + SM_AHI + off) = make_uint2(*(uint32_t*)&hp0, *(uint32_t*)&hp1);
        *(uint2*)(smem + SM_ALO + off) = make_uint2(*(uint32_t*)&lp0, *(uint32_t*)&lp1);
    }

    // W chunk issuer: chunk kc = K cols [kc*64, kc*64+64), hi+lo via cp.async
    auto issueW = [&](int kc, int buf) {
        uint32_t base = sb + (buf ? SM_W1 : SM_W0);
#pragma unroll
        for (int i = 0; i < 8; i++) {
            int v   = i * 512 + tid;      // 16B unit id, 4096 total (2048 hi + 2048 lo)
            int arr = v >> 11;
            int u   = v & 2047;
            int n   = u >> 3, uk = u & 7;
            uint32_t doff = n * 128 + ((uk ^ (n & 7)) << 4);
            const uint4* src = (arr ? g_Wlo4 : g_Whi4)
                             + ((size_t)(nb * 256 + n) * 32 + kc * 8 + uk);
            cp_async16(base + (arr ? SM_WLOFF : 0) + doff, src);
        }
        CP_COMMIT();
    };

    float acc[2][4][4];
#pragma unroll
    for (int a1 = 0; a1 < 2; a1++)
#pragma unroll
        for (int a2 = 0; a2 < 4; a2++)
#pragma unroll
            for (int a3 = 0; a3 < 4; a3++) acc[a1][a2][a3] = 0.0f;

    issueW(0, 0);

    for (int kc = 0; kc < 4; kc++) {
        const int buf = kc & 1;
        if (kc < 3) {
            issueW(kc + 1, buf ^ 1);
            asm volatile("cp.async.wait_group 1;" ::: "memory");
        } else {
            asm volatile("cp.async.wait_group 0;" ::: "memory");
        }
        __syncthreads();
        const uint32_t wbase = sb + (buf ? SM_W1 : SM_W0);

#pragma unroll
        for (int ks = 0; ks < 4; ks++) {
            const int kb = kc * 64 + ks * 16;
            const int g  = l >> 3;

            uint32_t ah[2][4], al[2][4];
#pragma unroll
            for (int mt = 0; mt < 2; mt++) {
                int r = wm * 32 + mt * 16 + ((g & 1) << 3) + (l & 7);
                int c = kb + ((g & 2) << 2);
                uint32_t off = r * 512 + ((((c >> 3) ^ (r & 7))) << 4);
                LDSM4(ah[mt], sb + SM_AHI + off);
                LDSM4(al[mt], sb + SM_ALO + off);
            }
#pragma unroll
            for (int ng = 0; ng < 2; ng++) {
                int n  = wn * 32 + ng * 16 + ((g & 2) << 2) + (l & 7);
                int kk = ks * 16 + ((g & 1) << 3);
                uint32_t woff = n * 128 + ((((kk >> 3) ^ (n & 7))) << 4);
                uint32_t bh[4], blo[4];
                LDSM4(bh,  wbase + woff);
                LDSM4(blo, wbase + SM_WLOFF + woff);
#pragma unroll
                for (int mt = 0; mt < 2; mt++) {
                    MMA(acc[mt][ng * 2 + 0], ah[mt], bh[0], bh[1]);
                    MMA(acc[mt][ng * 2 + 1], ah[mt], bh[2], bh[3]);
                    MMA(acc[mt][ng * 2 + 0], al[mt], bh[0], bh[1]);
                    MMA(acc[mt][ng * 2 + 1], al[mt], bh[2], bh[3]);
                    MMA(acc[mt][ng * 2 + 0], ah[mt], blo[0], blo[1]);
                    MMA(acc[mt][ng * 2 + 1], ah[mt], blo[2], blo[3]);
                }
            }
        }
        __syncthreads();    // compute done before next chunk overwrites its buffer
    }

    // -------- epilogue: activations -> smem staging --------
    float* xs = (float*)(smem + SM_XS);
    float* fs = (float*)(smem + SM_FS);
    const float* biasS = (const float*)(smem + SM_BIAS);
    const float* mkS   = (const float*)(smem + SM_MK);

#pragma unroll
    for (int mt = 0; mt < 2; mt++)
#pragma unroll
        for (int nt = 0; nt < 4; nt++) {
            int r0 = wm * 32 + mt * 16 + (l >> 2);
            int nl = wn * 32 + nt * 8 + 2 * (l & 3);
            bool isF = (nl >= 128);          // uniform per warp
            float* stg = isF ? fs : xs;
            int cc = nl & 127;
            float b0 = biasS[nl], b1 = biasS[nl + 1];
#pragma unroll
            for (int h = 0; h < 2; h++) {
                int r = r0 + h * 8;
                float z0 = acc[mt][nt][h * 2 + 0] + b0;
                float z1 = acc[mt][nt][h * 2 + 1] + b1;
                float v0, v1;
                if (isF) {
                    float mk = mkS[r];
                    z0 += mk; z1 += mk;
                    v0 = 1.0f / (1.0f + expf(-z0));
                    v1 = 1.0f / (1.0f + expf(-z1));
                } else {
                    v0 = tanhf(z0);
                    v1 = tanhf(z1);
                }
                stg[r * STG + cc]     = v0;
                stg[r * STG + cc + 1] = v1;
            }
        }
    __syncthreads();

    // -------- write g_X / g_F (coalesced float4) --------
#pragma unroll
    for (int i = 0; i < 8; i++) {
        int v   = i * 512 + tid;          // 4096 float4 slots (2048 X + 2048 F)
        int arr = v >> 11;
        int u   = v & 2047;
        int row = u >> 5;
        int c4  = (u & 31) * 4;
        const float* stg = arr ? fs : xs;
        float4 val = *(const float4*)(stg + row * STG + c4);
        float* dst = arr ? g_F : g_X;
        *(float4*)(dst + (size_t)(m0 + row) * D_ + nb * 128 + c4) = val;
    }

    // -------- fused chunk summary (pass1) --------
    if (tid < 128) {
        int dl = tid;
        float h = 0.0f, Aa = 1.0f;
#pragma unroll 8
        for (int t = 0; t < LCH; t++) {
            float f = fs[t * STG + dl];
            float x = xs[t * STG + dl];
            float om = 1.0f - f;
            h = fmaf(f, x, om * h);
            Aa *= om;
        }
        int b = m0 / T_;
        int c = (m0 % T_) / LCH;
        int ch = b * D_ + nb * 128 + dl;
        g_A [c * NCHAN + ch] = Aa;
        g_Hl[c * NCHAN + ch] = h;
    }
}

// ---------------------------------------------------------------------------
// Scan pass 2: per-channel combine over 64 chunk summaries.
// ---------------------------------------------------------------------------
__global__ __launch_bounds__(256)
void scan_pass2()
{
    const int ch = blockIdx.x * blockDim.x + threadIdx.x;
    float h = 0.0f;
#pragma unroll 8
    for (int c = 0; c < NCH; c++) {
        g_H0[c * NCHAN + ch] = h;
        h = fmaf(g_A[c * NCHAN + ch], h, g_Hl[c * NCHAN + ch]);
    }
}

// ---------------------------------------------------------------------------
// Scan pass 3: re-run each chunk from its entry state, write output.
// ---------------------------------------------------------------------------
__global__ __launch_bounds__(256)
void scan_pass3(float* __restrict__ out)
{
    const int b = blockIdx.x / NCH;
    const int c = blockIdx.x % NCH;
    const int d = threadIdx.x;
    const int ch = b * D_ + d;

    float h = g_H0[c * NCHAN + ch];
    size_t idx = ((size_t)(b * T_ + c * LCH)) * D_ + d;
#pragma unroll 8
    for (int t = 0; t < LCH; t++) {
        float f = g_F[idx];
        float x = g_X[idx];
        h = fmaf(f, x - h, h);
        out[idx] = h;
        idx += D_;
    }
}

extern "C" void kernel_launch(void* const* d_in, const int* in_sizes, int n_in,
                              void* d_out, int out_size)
{
    const float* inputs = (const float*)d_in[0];
    const float* mask   = (const float*)d_in[1];
    const float* W_in   = (const float*)d_in[2];
    const float* b_in   = (const float*)d_in[3];
    const float* W_f    = (const float*)d_in[4];
    const float* b_f    = (const float*)d_in[5];
    float* out = (float*)d_out;

    cudaFuncSetAttribute(gemm_mma_kernel, cudaFuncAttributeMaxDynamicSharedMemorySize, SM_TOTAL);

    wsplit_kernel<<<(N_TOT * K_ + 255) / 256, 256>>>(W_in, W_f);
    gemm_mma_kernel<<<(M_ / 64) * 2, 512, SM_TOTAL>>>(inputs, b_in, b_f, mask);
    scan_pass2<<<NCHAN / 256, 256>>>();
    scan_pass3<<<B_ * NCH, 256>>>(out);
}

// round 7
// speedup vs baseline: 5.4568x; 1.1823x over previous
#include <cuda_runtime.h>
#include <cuda_bf16.h>
#include <math.h>
#include <stdint.h>

// ---------------- problem constants ----------------
#define B_  8
#define T_  4096
#define D_  256
#define M_  (B_ * T_)      // 32768
#define K_  256
#define N_TOT 512

// ---------------- scan chunking ----------------
#define LCH 64
#define NCH (T_ / LCH)     // 64 chunks per batch
#define NBLK ((M_ / LCH) * 2)   // 1024 gemm blocks

// ---------------- scratch (static device allocations) ----------------
// W split, PERMUTED row order: p = nb*256 + branch*128 + (d&127), nb = d>>7.
__device__ uint4 g_Whi4[(N_TOT * K_) / 8];
__device__ uint4 g_Wlo4[(N_TOT * K_) / 8];
// decoupled-lookback state: per (block, local-channel)
__device__ float    g_SA [NBLK * 128];   // chunk decay product
__device__ float    g_SHl[NBLK * 128];   // chunk local final h (h0=0)
__device__ float    g_SHI[NBLK * 128];   // inclusive state after chunk
__device__ uint32_t g_flag[NBLK * 128];  // 0=none, 1=aggregate, 2=inclusive

// ---------------- smem layout ----------------
#define SM_AHI   0
#define SM_ALO   32768
#define SM_W0    65536
#define SM_W1    131072
#define SM_WLOFF 32768
#define SM_BIAS  196608
#define SM_MK    197632
#define SM_TOTAL 197888
#define SM_XS    0
#define SM_FS    36864
#define STG      136

// ---------------- asm helpers (base sm_103 features only) ----------------
__device__ __forceinline__ uint32_t smem_u32(const void* p) {
    uint32_t a;
    asm("{ .reg .u64 t; cvta.to.shared.u64 t, %1; cvt.u32.u64 %0, t; }" : "=r"(a) : "l"(p));
    return a;
}
#define LDSM4(r, addr) asm volatile( \
    "ldmatrix.sync.aligned.m8n8.x4.shared.b16 {%0,%1,%2,%3}, [%4];" \
    : "=r"((r)[0]), "=r"((r)[1]), "=r"((r)[2]), "=r"((r)[3]) : "r"(addr))
#define MMA(d, a, b0v, b1v) asm volatile( \
    "mma.sync.aligned.m16n8k16.row.col.f32.bf16.bf16.f32 " \
    "{%0,%1,%2,%3}, {%4,%5,%6,%7}, {%8,%9}, {%0,%1,%2,%3};" \
    : "+f"((d)[0]), "+f"((d)[1]), "+f"((d)[2]), "+f"((d)[3]) \
    : "r"((a)[0]), "r"((a)[1]), "r"((a)[2]), "r"((a)[3]), "r"(b0v), "r"(b1v))
__device__ __forceinline__ void cp_async16(uint32_t dst, const void* src) {
    asm volatile("cp.async.cg.shared.global [%0], [%1], 16;" :: "r"(dst), "l"(src));
}
#define CP_COMMIT() asm volatile("cp.async.commit_group;" ::: "memory")
__device__ __forceinline__ void st_release_u32(uint32_t* p, uint32_t v) {
    asm volatile("st.global.release.gpu.b32 [%0], %1;" :: "l"(p), "r"(v) : "memory");
}
__device__ __forceinline__ uint32_t ld_acquire_u32(const uint32_t* p) {
    uint32_t v;
    asm volatile("ld.global.acquire.gpu.b32 %0, [%1];" : "=r"(v) : "l"(p) : "memory");
    return v;
}

// ---------------------------------------------------------------------------
// W precompute (fp32 -> hi/lo bf16, permuted) + zero lookback flags.
// 131072 threads == NBLK*128 flag slots exactly.
// ---------------------------------------------------------------------------
__global__ void wsplit_kernel(const float* __restrict__ W_in, const float* __restrict__ W_f)
{
    int i = blockIdx.x * blockDim.x + threadIdx.x;
    if (i >= N_TOT * K_) return;
    g_flag[i] = 0u;
    int p = i >> 8, k = i & 255;
    int nb = p >> 8;
    int rem = p & 255;
    int branch = rem >> 7;
    int d = nb * 128 + (rem & 127);
    float v = branch ? W_f[d * K_ + k] : W_in[d * K_ + k];
    __nv_bfloat16 hi = __float2bfloat16_rn(v);
    ((__nv_bfloat16*)g_Whi4)[i] = hi;
    ((__nv_bfloat16*)g_Wlo4)[i] = __float2bfloat16_rn(v - __bfloat162float(hi));
}

// ---------------------------------------------------------------------------
// Fused: split-bf16 mma GEMM + activations + decoupled-lookback scan + output.
// grid = 1024 blocks (512 m-chunks x 2 n-halves), 512 threads.
// ---------------------------------------------------------------------------
__global__ __launch_bounds__(512, 1)
void fused_kernel(const float* __restrict__ A,
                  const float* __restrict__ b_in,
                  const float* __restrict__ b_f,
                  const float* __restrict__ mask,
                  float* __restrict__ out)
{
    extern __shared__ __align__(16) char smem[];
    const uint32_t sb = smem_u32(smem);
    const int tid = threadIdx.x;
    const int w   = tid >> 5, l = tid & 31;
    const int wm  = w >> 3;
    const int wn  = w & 7;
    const int bid = blockIdx.x;
    const int m0  = (bid >> 1) * 64;
    const int nb  = bid & 1;

    for (int i = tid; i < 256; i += 512) {
        int branch = i >> 7;
        int d = nb * 128 + (i & 127);
        *(float*)(smem + SM_BIAS + i * 4) = branch ? b_f[d] : b_in[d];
    }
    if (tid < 64) *(float*)(smem + SM_MK + tid * 4) = mask[m0 + tid] * 10000.0f;

    // A tile [64][256] fp32 -> smem hi/lo bf16 (swizzled, full K)
#pragma unroll
    for (int i = 0; i < 8; i++) {
        int v   = i * 512 + tid;
        int row = v >> 6;
        int col = (v & 63) * 4;
        float4 a = *(const float4*)(A + (size_t)(m0 + row) * K_ + col);
        __nv_bfloat16 h0 = __float2bfloat16_rn(a.x), h1 = __float2bfloat16_rn(a.y),
                      h2 = __float2bfloat16_rn(a.z), h3 = __float2bfloat16_rn(a.w);
        __nv_bfloat162 hp0 = {h0, h1}, hp1 = {h2, h3};
        __nv_bfloat162 lp0 = __floats2bfloat162_rn(a.x - __bfloat162float(h0),
                                                   a.y - __bfloat162float(h1));
        __nv_bfloat162 lp1 = __floats2bfloat162_rn(a.z - __bfloat162float(h2),
                                                   a.w - __bfloat162float(h3));
        uint32_t off = row * 512 + ((((col >> 3) ^ (row & 7))) << 4) + (col & 7) * 2;
        *(uint2*)(smem + SM_AHI + off) = make_uint2(*(uint32_t*)&hp0, *(uint32_t*)&hp1);
        *(uint2*)(smem + SM_ALO + off) = make_uint2(*(uint32_t*)&lp0, *(uint32_t*)&lp1);
    }

    auto issueW = [&](int kc, int buf) {
        uint32_t base = sb + (buf ? SM_W1 : SM_W0);
#pragma unroll
        for (int i = 0; i < 8; i++) {
            int v   = i * 512 + tid;
            int arr = v >> 11;
            int u   = v & 2047;
            int n   = u >> 3, uk = u & 7;
            uint32_t doff = n * 128 + ((uk ^ (n & 7)) << 4);
            const uint4* src = (arr ? g_Wlo4 : g_Whi4)
                             + ((size_t)(nb * 256 + n) * 32 + kc * 8 + uk);
            cp_async16(base + (arr ? SM_WLOFF : 0) + doff, src);
        }
        CP_COMMIT();
    };

    float acc[2][4][4];
#pragma unroll
    for (int a1 = 0; a1 < 2; a1++)
#pragma unroll
        for (int a2 = 0; a2 < 4; a2++)
#pragma unroll
            for (int a3 = 0; a3 < 4; a3++) acc[a1][a2][a3] = 0.0f;

    issueW(0, 0);

    for (int kc = 0; kc < 4; kc++) {
        const int buf = kc & 1;
        if (kc < 3) {
            issueW(kc + 1, buf ^ 1);
            asm volatile("cp.async.wait_group 1;" ::: "memory");
        } else {
            asm volatile("cp.async.wait_group 0;" ::: "memory");
        }
        __syncthreads();
        const uint32_t wbase = sb + (buf ? SM_W1 : SM_W0);

#pragma unroll
        for (int ks = 0; ks < 4; ks++) {
            const int kb = kc * 64 + ks * 16;
            const int g  = l >> 3;

            uint32_t ah[2][4], al[2][4];
#pragma unroll
            for (int mt = 0; mt < 2; mt++) {
                int r = wm * 32 + mt * 16 + ((g & 1) << 3) + (l & 7);
                int c = kb + ((g & 2) << 2);
                uint32_t off = r * 512 + ((((c >> 3) ^ (r & 7))) << 4);
                LDSM4(ah[mt], sb + SM_AHI + off);
                LDSM4(al[mt], sb + SM_ALO + off);
            }
#pragma unroll
            for (int ng = 0; ng < 2; ng++) {
                int n  = wn * 32 + ng * 16 + ((g & 2) << 2) + (l & 7);
                int kk = ks * 16 + ((g & 1) << 3);
                uint32_t woff = n * 128 + ((((kk >> 3) ^ (n & 7))) << 4);
                uint32_t bh[4], blo[4];
                LDSM4(bh,  wbase + woff);
                LDSM4(blo, wbase + SM_WLOFF + woff);
#pragma unroll
                for (int mt = 0; mt < 2; mt++) {
                    MMA(acc[mt][ng * 2 + 0], ah[mt], bh[0], bh[1]);
                    MMA(acc[mt][ng * 2 + 1], ah[mt], bh[2], bh[3]);
                    MMA(acc[mt][ng * 2 + 0], al[mt], bh[0], bh[1]);
                    MMA(acc[mt][ng * 2 + 1], al[mt], bh[2], bh[3]);
                    MMA(acc[mt][ng * 2 + 0], ah[mt], blo[0], blo[1]);
                    MMA(acc[mt][ng * 2 + 1], ah[mt], blo[2], blo[3]);
                }
            }
        }
        __syncthreads();
    }

    // -------- epilogue: activations -> smem staging --------
    float* xs = (float*)(smem + SM_XS);
    float* fs = (float*)(smem + SM_FS);
    const float* biasS = (const float*)(smem + SM_BIAS);
    const float* mkS   = (const float*)(smem + SM_MK);

#pragma unroll
    for (int mt = 0; mt < 2; mt++)
#pragma unroll
        for (int nt = 0; nt < 4; nt++) {
            int r0 = wm * 32 + mt * 16 + (l >> 2);
            int nl = wn * 32 + nt * 8 + 2 * (l & 3);
            bool isF = (nl >= 128);
            float* stg = isF ? fs : xs;
            int cc = nl & 127;
            float b0 = biasS[nl], b1 = biasS[nl + 1];
#pragma unroll
            for (int h = 0; h < 2; h++) {
                int r = r0 + h * 8;
                float z0 = acc[mt][nt][h * 2 + 0] + b0;
                float z1 = acc[mt][nt][h * 2 + 1] + b1;
                float v0, v1;
                if (isF) {
                    float mk = mkS[r];
                    z0 += mk; z1 += mk;
                    v0 = 1.0f / (1.0f + expf(-z0));
                    v1 = 1.0f / (1.0f + expf(-z1));
                } else {
                    v0 = tanhf(z0);
                    v1 = tanhf(z1);
                }
                stg[r * STG + cc]     = v0;
                stg[r * STG + cc + 1] = v1;
            }
        }
    __syncthreads();

    // -------- lookback scan: 128 threads, one per local channel --------
    if (tid < 128) {
        const int dl = tid;
        const int slot = bid * 128 + dl;

        // local chunk summary (h0 = 0)
        float hl = 0.0f, Aa = 1.0f;
#pragma unroll 8
        for (int t = 0; t < LCH; t++) {
            float f = fs[t * STG + dl];
            float x = xs[t * STG + dl];
            float om = 1.0f - f;
            hl = fmaf(f, x, om * hl);
            Aa *= om;
        }

        const int c = (bid >> 1) & (NCH - 1);   // chunk index within batch
        float h0 = 0.0f;
        if (c != 0) {
            // publish aggregate
            g_SA [slot] = Aa;
            g_SHl[slot] = hl;
            st_release_u32(&g_flag[slot], 1u);
            // walk predecessors (same nb -> stride 2 in bid)
            float mult = 1.0f;
            int p = slot - 256;                 // (bid-2)*128 + dl
            while (true) {
                uint32_t f;
                do { f = ld_acquire_u32(&g_flag[p]); } while (f == 0u);
                if (f == 2u) { h0 = fmaf(mult, g_SHI[p], h0); break; }
                h0 = fmaf(mult, g_SHl[p], h0);
                mult *= g_SA[p];
                p -= 256;
            }
        }
        // publish inclusive state
        g_SHI[slot] = fmaf(Aa, h0, hl);
        st_release_u32(&g_flag[slot], 2u);

        // final scan with correct entry state; write output directly
        float h = h0;
        float* op = out + (size_t)m0 * D_ + nb * 128 + dl;
#pragma unroll 8
        for (int t = 0; t < LCH; t++) {
            float f = fs[t * STG + dl];
            float x = xs[t * STG + dl];
            h = fmaf(f, x - h, h);
            op[(size_t)t * D_] = h;
        }
    }
}

extern "C" void kernel_launch(void* const* d_in, const int* in_sizes, int n_in,
                              void* d_out, int out_size)
{
    const float* inputs = (const float*)d_in[0];
    const float* mask   = (const float*)d_in[1];
    const float* W_in   = (const float*)d_in[2];
    const float* b_in   = (const float*)d_in[3];
    const float* W_f    = (const float*)d_in[4];
    const float* b_f    = (const float*)d_in[5];
    float* out = (float*)d_out;

    cudaFuncSetAttribute(fused_kernel, cudaFuncAttributeMaxDynamicSharedMemorySize, SM_TOTAL);

    wsplit_kernel<<<(N_TOT * K_ + 255) / 256, 256>>>(W_in, W_f);
    fused_kernel<<<NBLK, 512, SM_TOTAL>>>(inputs, b_in, b_f, mask, out);
}